// round 12
// baseline (speedup 1.0000x reference)
#include <cuda_runtime.h>
#include <cuda_fp16.h>
#include <math.h>
typedef unsigned int uint;
typedef unsigned short ushort;

#define B_   64
#define T_   512
#define H_   1024
#define L_   2
#define G_   4096
#define K2_  2048
#define NBLK 128

// lstm_seq smem plan (float units)
#define WH_OFF 0          // W hi fp16 fragments: 4096 uint4
#define WL_OFF 16384      // W lo fp16 fragments
#define HT_OFF 32768      // h ring: 3 bufs x (64 rows x 136 halfs) = 13056 floats
#define GT_OFF 45824      // gate exchange: 4 x 2112 floats
#define GT_GRP 2112
#define CS_OFF 54272      // cell state: 512 floats
#define SM_FLOATS 54784
#define SM_BYTES  (SM_FLOATS * 4)   // 219,136 B

__device__ float  g_gin[(size_t)B_ * T_ * G_];
__device__ float  g_mid[(size_t)B_ * T_ * H_];
__device__ ushort g_hf[2][B_ * H_];        // h single fp16, ping-pong parity
__device__ unsigned g_grp[256];            // 8 group counters, 128B apart
__device__ unsigned g_root = 0;
__device__ unsigned g_gen = 0;

__device__ __forceinline__ void mma_f16(float4& c, const uint4& a, uint b0, uint b1) {
    asm volatile(
        "mma.sync.aligned.m16n8k16.row.col.f32.f16.f16.f32 "
        "{%0,%1,%2,%3}, {%4,%5,%6,%7}, {%8,%9}, {%0,%1,%2,%3};"
        : "+f"(c.x), "+f"(c.y), "+f"(c.z), "+f"(c.w)
        : "r"(a.x), "r"(a.y), "r"(a.z), "r"(a.w), "r"(b0), "r"(b1));
}
__device__ __forceinline__ uint h2pack(float2 v) {
    __half2 h = __float22half2_rn(v);
    return *(uint*)&h;
}
__device__ __forceinline__ uint2 hsplit(float2 v) {
    __half2 h = __float22half2_rn(v);
    float lx = __half2float(__low2half(h));
    float ly = __half2float(__high2half(h));
    __half2 l = __float22half2_rn(make_float2(v.x - lx, v.y - ly));
    uint2 o;
    o.x = *(uint*)&h;
    o.y = *(uint*)&l;
    return o;
}
__device__ __forceinline__ float sigmoidf_(float x) { return __fdividef(1.0f, 1.0f + expf(-x)); }
__device__ __forceinline__ void cp_async16u(const ushort* smem_dst, const ushort* gsrc) {
    unsigned sa = (unsigned)__cvta_generic_to_shared((void*)smem_dst);
    asm volatile("cp.async.cg.shared.global [%0], [%1], 16;" :: "r"(sa), "l"(gsrc));
}

// Tree grid barrier: 8 padded group counters -> root -> release gen.
__device__ __forceinline__ void grid_barrier(int jb) {
    __syncthreads();
    if (threadIdx.x == 0) {
        asm volatile("fence.acq_rel.gpu;" ::: "memory");
        unsigned old;
        asm volatile("ld.relaxed.gpu.u32 %0, [%1];" : "=r"(old) : "l"(&g_gen));
        unsigned prev = atomicAdd(&g_grp[(jb & 7) * 32], 1u);
        bool done = false;
        if (prev == 15u) {
            unsigned pr = atomicAdd(&g_root, 1u);
            if (pr == 7u) {
#pragma unroll
                for (int i = 0; i < 8; i++)
                    asm volatile("st.relaxed.gpu.u32 [%0], %1;"
                                 :: "l"(&g_grp[i * 32]), "r"(0u));
                asm volatile("st.relaxed.gpu.u32 [%0], %1;" :: "l"(&g_root), "r"(0u));
                asm volatile("st.release.gpu.u32 [%0], %1;" :: "l"(&g_gen), "r"(old + 1u));
                done = true;
            }
        }
        if (!done) {
            unsigned cur;
            do { asm volatile("ld.acquire.gpu.u32 %0, [%1];" : "=r"(cur) : "l"(&g_gen)); }
            while (cur == old);
        }
    }
    __syncthreads();
}

// ---------------------------------------------------------------------------
// Input GEMM (2-term fp16) — unchanged from R10 (passing).
// ---------------------------------------------------------------------------
__global__ void __launch_bounds__(256, 2) lstm_in_gemm(
    const float* __restrict__ A, const float* __restrict__ Wl,
    const float* __restrict__ bl, float* __restrict__ C)
{
    __shared__ uint4 Af[512];
    __shared__ uint4 Bf[512];

    const int tid = threadIdx.x, n0 = blockIdx.x * 64, m0 = blockIdx.y * 128;
    const int lane = tid & 31, warp = tid >> 5;
    const int wm = warp >> 1, wn = warp & 1;
    const int g = lane >> 2, tg = lane & 3;

    const size_t rA0 = (size_t)(m0 + warp * 16 + g) * H_;
    const size_t rA1 = rA0 + (size_t)8 * H_;
    const size_t rB0 = (size_t)(n0 + warp * 8 + g) * K2_;

    float2 a0v, a1v, a2v, a3v, b0v, b1v;
    float4 cc[2][4];
#pragma unroll
    for (int i = 0; i < 2; i++)
#pragma unroll
        for (int j = 0; j < 4; j++) cc[i][j] = make_float4(0.f, 0.f, 0.f, 0.f);

#define LOADG(kb_) do {                                       \
    a0v = *(const float2*)&A[rA0 + (kb_) + tg * 2];           \
    a1v = *(const float2*)&A[rA1 + (kb_) + tg * 2];           \
    a2v = *(const float2*)&A[rA0 + (kb_) + 8 + tg * 2];       \
    a3v = *(const float2*)&A[rA1 + (kb_) + 8 + tg * 2];       \
    b0v = *(const float2*)&Wl[rB0 + (kb_) + tg * 2];          \
    b1v = *(const float2*)&Wl[rB0 + (kb_) + 8 + tg * 2];      \
} while (0)

#define STAGE(buf_) do {                                      \
    Af[((buf_) * 8 + warp) * 32 + lane] =                     \
        make_uint4(h2pack(a0v), h2pack(a1v), h2pack(a2v), h2pack(a3v)); \
    uint2 t0 = hsplit(b0v), t1 = hsplit(b1v);                 \
    Bf[((buf_) * 8 + warp) * 32 + lane] = make_uint4(t0.x, t1.x, t0.y, t1.y); \
} while (0)

    LOADG(0);
    STAGE(0);
    __syncthreads();

    for (int it = 0; it < 64; it++) {
        const int buf = it & 1;
        if (it < 63) LOADG((it + 1) * 16);

        uint4 aF0 = Af[(buf * 8 + wm * 2 + 0) * 32 + lane];
        uint4 aF1 = Af[(buf * 8 + wm * 2 + 1) * 32 + lane];
#pragma unroll
        for (int nt = 0; nt < 4; nt++) {
            uint4 bv = Bf[(buf * 8 + wn * 4 + nt) * 32 + lane];
            mma_f16(cc[0][nt], aF0, bv.x, bv.y);
            mma_f16(cc[1][nt], aF1, bv.x, bv.y);
            mma_f16(cc[0][nt], aF0, bv.z, bv.w);
            mma_f16(cc[1][nt], aF1, bv.z, bv.w);
        }
        if (it < 63) STAGE((it + 1) & 1);
        __syncthreads();
    }
#undef LOADG
#undef STAGE

#pragma unroll
    for (int mt = 0; mt < 2; mt++)
#pragma unroll
        for (int nt = 0; nt < 4; nt++) {
            const int row = m0 + wm * 32 + mt * 16 + g;
            const int col = n0 + wn * 32 + nt * 8 + 2 * tg;
            const float2 bias = *(const float2*)&bl[col];
            float4 v = cc[mt][nt];
            *(float2*)&C[(size_t)row * G_ + col] = make_float2(v.x + bias.x, v.y + bias.y);
            *(float2*)&C[(size_t)(row + 8) * G_ + col] = make_float2(v.z + bias.x, v.w + bias.y);
        }
}

// ---------------------------------------------------------------------------
// Persistent recurrence (2-term fp16), 512 thr (16 warps), 128 blocks.
// K split 4 ways (kw), N split 4 ways (wn). 128-k chunks, 3-buffer ring,
// ONE __syncthreads per chunk.
// ---------------------------------------------------------------------------
__global__ void __launch_bounds__(512, 1) lstm_seq(
    const float* __restrict__ Wl, const float* __restrict__ gin,
    const float* __restrict__ c0l, const float* __restrict__ h0l,
    ushort* __restrict__ hF0, ushort* __restrict__ hF1,
    float* __restrict__ layer_out, float* __restrict__ outp, int l)
{
    extern __shared__ float sm[];
    uint4*  WsH  = (uint4*)(sm + WH_OFF);
    uint4*  WsL  = (uint4*)(sm + WL_OFF);
    ushort* hbuf = (ushort*)(sm + HT_OFF);   // 3 bufs x [64 b][136 halfs]
    float*  gt   = sm + GT_OFF;              // 4 slabs
    float*  cs   = sm + CS_OFF;

    const int tid = threadIdx.x, jb = blockIdx.x;
    const int lane = tid & 31, warp = tid >> 5;
    const int wn = warp & 3, kw = warp >> 2;

    // --- W fragment staging (once per layer), fp16 hi/lo
#pragma unroll 1
    for (int q = 0; q < 8; q++) {
        const int fi = q * 512 + tid;               // 0..4095
        const int ln = fi & 31, kc = (fi >> 5) & 63, mt = fi >> 11;
        const int colc = mt * 16 + (ln >> 2);
        const int colc8 = colc + 8;
        const int gr  = (colc  >> 3) * H_ + jb * 8 + (colc  & 7);
        const int gr8 = (colc8 >> 3) * H_ + jb * 8 + (colc8 & 7);
        const int k0 = kc * 16 + (ln & 3) * 2;
        const float* w0 = Wl + (size_t)gr  * K2_ + H_;
        const float* w8 = Wl + (size_t)gr8 * K2_ + H_;
        uint2 s0 = hsplit(*(const float2*)(w0 + k0));
        uint2 s1 = hsplit(*(const float2*)(w8 + k0));
        uint2 s2 = hsplit(*(const float2*)(w0 + k0 + 8));
        uint2 s3 = hsplit(*(const float2*)(w8 + k0 + 8));
        WsH[fi] = make_uint4(s0.x, s1.x, s2.x, s3.x);
        WsL[fi] = make_uint4(s0.y, s1.y, s2.y, s3.y);
    }
    cs[tid] = c0l[(tid >> 3) * H_ + jb * 8 + (tid & 7)];
    {   // h0 -> parity-0 buffer (this block's 8-k slice)
        const int k = jb * 8 + (tid >> 6), b = tid & 63;
        __half hh = __float2half_rn(h0l[b * H_ + k]);
        hF0[b * 1024 + k] = *(ushort*)&hh;
    }

    const int b_pw = tid & 63;
    const int jj   = tid >> 6;               // 0..7: one gate col per thread
    const int sb = tid >> 3;                 // staging batch row 0..63
    const int sk0 = (tid & 7) * 16;          // halfs within 128-k chunk

    for (int t = 0; t < T_; t++) {
        const ushort* rH = (t & 1) ? hF1 : hF0;
        ushort*       wH = (t & 1) ? hF0 : hF1;

        const float* gp = gin + ((size_t)b_pw * T_ + t) * G_ + jb * 8 + jj;
        float pf = __ldg(gp);
        float pi = __ldg(gp + H_);
        float pg = __ldg(gp + 2 * H_);
        float po = __ldg(gp + 3 * H_);

        grid_barrier(jb);

        // prologue: chunks 0,1 -> bufs 0,1  (chunk = 64 b x 128 k fp16)
#pragma unroll
        for (int i = 0; i < 2; i++) {
            ushort* d = hbuf + i * 8704 + sb * 136 + sk0;
            const ushort* s = rH + sb * 1024 + i * 128 + sk0;
            cp_async16u(d, s);
            cp_async16u(d + 8, s + 8);
            asm volatile("cp.async.commit_group;");
        }

        float4 aHH[2][2], aLH[2][2];
#pragma unroll
        for (int i = 0; i < 2; i++)
#pragma unroll
            for (int j = 0; j < 2; j++) {
                aHH[i][j] = make_float4(0.f, 0.f, 0.f, 0.f);
                aLH[i][j] = make_float4(0.f, 0.f, 0.f, 0.f);
            }

#pragma unroll 1
        for (int c = 0; c < 8; c++) {
            if (c < 7) asm volatile("cp.async.wait_group 1;");
            else       asm volatile("cp.async.wait_group 0;");
            __syncthreads();   // chunk c ready; also WAR guard for buf (c+2)%3

            if (c < 6) {
                const int nb = (c + 2) % 3;
                ushort* d = hbuf + nb * 8704 + sb * 136 + sk0;
                const ushort* s = rH + sb * 1024 + (c + 2) * 128 + sk0;
                cp_async16u(d, s);
                cp_async16u(d + 8, s + 8);
                asm volatile("cp.async.commit_group;");
            }

            const ushort* hc = hbuf + (c % 3) * 8704;
#pragma unroll
            for (int r = 0; r < 2; r++) {
                const int kloc = kw * 2 + r;          // k16 within chunk (0..7)
                const int kg = c * 8 + kloc;          // global k16 (0..63)
                uint4 aH0 = WsH[kg * 32 + lane];
                uint4 aH1 = WsH[(64 + kg) * 32 + lane];
                uint4 aL0 = WsL[kg * 32 + lane];
                uint4 aL1 = WsL[(64 + kg) * 32 + lane];
#pragma unroll
                for (int nt = 0; nt < 2; nt++) {
                    const int col = (wn * 2 + nt) * 8 + (lane >> 2);
                    const int off = col * 136 + kloc * 16 + (lane & 3) * 2;
                    uint b0 = *(const uint*)(hc + off);
                    uint b1 = *(const uint*)(hc + off + 8);
                    mma_f16(aHH[0][nt], aH0, b0, b1);
                    mma_f16(aHH[1][nt], aH1, b0, b1);
                    mma_f16(aLH[0][nt], aL0, b0, b1);
                    mma_f16(aLH[1][nt], aL1, b0, b1);
                }
            }
        }

        // gate partials -> this kw group's slab
        float* slab = gt + kw * GT_GRP;
#pragma unroll
        for (int mt = 0; mt < 2; mt++)
#pragma unroll
            for (int nt = 0; nt < 2; nt++) {
                float4 v;
                v.x = aHH[mt][nt].x + aLH[mt][nt].x;
                v.y = aHH[mt][nt].y + aLH[mt][nt].y;
                v.z = aHH[mt][nt].z + aLH[mt][nt].z;
                v.w = aHH[mt][nt].w + aLH[mt][nt].w;
                const int colr = mt * 16 + (lane >> 2);
                const int bcol = (wn * 2 + nt) * 8 + (lane & 3) * 2;
                *(float2*)&slab[colr * 66 + bcol] = make_float2(v.x, v.y);
                *(float2*)&slab[(colr + 8) * 66 + bcol] = make_float2(v.z, v.w);
            }
        __syncthreads();

        // pointwise: thread owns (batch b_pw, gate col jj)
        const int gi_ = jj * 66 + b_pw;
        float xf = gt[gi_]                 + gt[GT_GRP + gi_]
                 + gt[2 * GT_GRP + gi_]    + gt[3 * GT_GRP + gi_] + pf;
        const int gi2 = (8 + jj) * 66 + b_pw;
        float xi = gt[gi2]                 + gt[GT_GRP + gi2]
                 + gt[2 * GT_GRP + gi2]    + gt[3 * GT_GRP + gi2] + pi;
        const int gi3 = (16 + jj) * 66 + b_pw;
        float xg = gt[gi3]                 + gt[GT_GRP + gi3]
                 + gt[2 * GT_GRP + gi3]    + gt[3 * GT_GRP + gi3] + pg;
        const int gi4 = (24 + jj) * 66 + b_pw;
        float xo = gt[gi4]                 + gt[GT_GRP + gi4]
                 + gt[2 * GT_GRP + gi4]    + gt[3 * GT_GRP + gi4] + po;

        float f = sigmoidf_(xf), ig = sigmoidf_(xi);
        float gv = tanhf(xg),    o  = sigmoidf_(xo);
        float cv = f * cs[tid] + ig * gv;
        float hv = o * tanhf(cv);
        cs[tid] = cv;

        __half hh = __float2half_rn(hv);
        wH[b_pw * 1024 + jb * 8 + jj] = *(ushort*)&hh;
        layer_out[((size_t)b_pw * T_ + t) * H_ + jb * 8 + jj] = hv;
        if (t == T_ - 1) {
            size_t hb2 = (size_t)B_ * T_ * H_ + (size_t)l * B_ * H_ +
                         (size_t)b_pw * H_ + jb * 8 + jj;
            outp[hb2] = hv;
            outp[hb2 + (size_t)L_ * B_ * H_] = cv;
        }
    }
}

extern "C" void kernel_launch(void* const* d_in, const int* in_sizes, int n_in,
                              void* d_out, int out_size)
{
    const float* x  = (const float*)d_in[0];
    const float* W  = (const float*)d_in[1];
    const float* bs = (const float*)d_in[2];
    const float* h0 = (const float*)d_in[3];
    const float* c0 = (const float*)d_in[4];
    float* out = (float*)d_out;

    float *gin, *mid;
    ushort* hf;
    cudaGetSymbolAddress((void**)&gin, g_gin);
    cudaGetSymbolAddress((void**)&mid, g_mid);
    cudaGetSymbolAddress((void**)&hf, g_hf);
    ushort* hF0 = hf;
    ushort* hF1 = hf + B_ * H_;

    cudaFuncSetAttribute(lstm_seq, cudaFuncAttributeMaxDynamicSharedMemorySize,
                         SM_BYTES);

    for (int l = 0; l < L_; l++) {
        const float* layer_in  = (l == 0) ? x   : mid;
        float*       layer_out = (l == 0) ? mid : out;
        const float* Wl = W  + (size_t)l * G_ * K2_;
        const float* bl = bs + (size_t)l * G_;

        lstm_in_gemm<<<dim3(64, 256), 256>>>(layer_in, Wl, bl, gin);
        lstm_seq<<<NBLK, 512, SM_BYTES>>>(Wl, gin,
                                          c0 + (size_t)l * B_ * H_,
                                          h0 + (size_t)l * B_ * H_,
                                          hF0, hF1, layer_out, out, l);
    }
}

// round 13
// speedup vs baseline: 1.1999x; 1.1999x over previous
#include <cuda_runtime.h>
#include <cuda_fp16.h>
#include <math.h>
typedef unsigned int uint;
typedef unsigned short ushort;

#define B_   64
#define T_   512
#define H_   1024
#define L_   2
#define G_   4096
#define K2_  2048
#define NBLK 128

// lstm_seq smem plan (float units)
#define WH_OFF 0          // W hi fp16 fragments: 4096 uint4
#define WL_OFF 16384      // W lo fp16 fragments
#define HT_OFF 32768      // h ring: 3 bufs x (64 rows x 72 halfs) = 6912 floats
#define GT_OFF 39680      // gate exchange: 2 x 2112 floats
#define GT_GRP 2112
#define CS_OFF 43904      // cell state: 512 floats
#define SM_FLOATS 44416
#define SM_BYTES  (SM_FLOATS * 4)

__device__ float  g_gin[(size_t)B_ * T_ * G_];
__device__ float  g_mid[(size_t)B_ * T_ * H_];
__device__ ushort g_hf[2][B_ * H_];        // h single fp16, ping-pong parity
__device__ unsigned g_grp[256];            // 8 group counters, 128B apart
__device__ unsigned g_root = 0;
__device__ unsigned g_gen = 0;

__device__ __forceinline__ void mma_f16(float4& c, const uint4& a, uint b0, uint b1) {
    asm volatile(
        "mma.sync.aligned.m16n8k16.row.col.f32.f16.f16.f32 "
        "{%0,%1,%2,%3}, {%4,%5,%6,%7}, {%8,%9}, {%0,%1,%2,%3};"
        : "+f"(c.x), "+f"(c.y), "+f"(c.z), "+f"(c.w)
        : "r"(a.x), "r"(a.y), "r"(a.z), "r"(a.w), "r"(b0), "r"(b1));
}
__device__ __forceinline__ uint h2pack(float2 v) {
    __half2 h = __float22half2_rn(v);
    return *(uint*)&h;
}
__device__ __forceinline__ uint2 hsplit(float2 v) {
    __half2 h = __float22half2_rn(v);
    float lx = __half2float(__low2half(h));
    float ly = __half2float(__high2half(h));
    __half2 l = __float22half2_rn(make_float2(v.x - lx, v.y - ly));
    uint2 o;
    o.x = *(uint*)&h;
    o.y = *(uint*)&l;
    return o;
}
__device__ __forceinline__ float sigmoidf_(float x) { return __fdividef(1.0f, 1.0f + expf(-x)); }
__device__ __forceinline__ void cp_async16u(const ushort* smem_dst, const ushort* gsrc) {
    unsigned sa = (unsigned)__cvta_generic_to_shared((void*)smem_dst);
    asm volatile("cp.async.cg.shared.global [%0], [%1], 16;" :: "r"(sa), "l"(gsrc));
}

// Tree grid barrier: 8 padded group counters -> root -> release gen.
__device__ __forceinline__ void grid_barrier(int jb) {
    __syncthreads();
    if (threadIdx.x == 0) {
        asm volatile("fence.acq_rel.gpu;" ::: "memory");
        unsigned old;
        asm volatile("ld.relaxed.gpu.u32 %0, [%1];" : "=r"(old) : "l"(&g_gen));
        unsigned prev = atomicAdd(&g_grp[(jb & 7) * 32], 1u);
        bool done = false;
        if (prev == 15u) {
            unsigned pr = atomicAdd(&g_root, 1u);
            if (pr == 7u) {
#pragma unroll
                for (int i = 0; i < 8; i++)
                    asm volatile("st.relaxed.gpu.u32 [%0], %1;"
                                 :: "l"(&g_grp[i * 32]), "r"(0u));
                asm volatile("st.relaxed.gpu.u32 [%0], %1;" :: "l"(&g_root), "r"(0u));
                asm volatile("st.release.gpu.u32 [%0], %1;" :: "l"(&g_gen), "r"(old + 1u));
                done = true;
            }
        }
        if (!done) {
            unsigned cur;
            do { asm volatile("ld.acquire.gpu.u32 %0, [%1];" : "=r"(cur) : "l"(&g_gen)); }
            while (cur == old);
        }
    }
    __syncthreads();
}

// ---------------------------------------------------------------------------
// Input GEMM (single-term fp16): gin[m,n] = A[m,0:H].W[n,0:H] + bias[n]
// Block 128Mx64N, BK=16, 256 thr, warp tile 32x32. x and W single fp16.
// ---------------------------------------------------------------------------
__global__ void __launch_bounds__(256, 2) lstm_in_gemm(
    const float* __restrict__ A, const float* __restrict__ Wl,
    const float* __restrict__ bl, float* __restrict__ C)
{
    __shared__ uint4 Af[512];    // [buf2][mt8][lane32] fp16 A-frag
    __shared__ uint2 Bf[512];    // [buf2][nt8][lane32] = (b0h, b1h)

    const int tid = threadIdx.x, n0 = blockIdx.x * 64, m0 = blockIdx.y * 128;
    const int lane = tid & 31, warp = tid >> 5;
    const int wm = warp >> 1, wn = warp & 1;
    const int g = lane >> 2, tg = lane & 3;

    const size_t rA0 = (size_t)(m0 + warp * 16 + g) * H_;
    const size_t rA1 = rA0 + (size_t)8 * H_;
    const size_t rB0 = (size_t)(n0 + warp * 8 + g) * K2_;

    float2 a0v, a1v, a2v, a3v, b0v, b1v;
    float4 cc[2][4];
#pragma unroll
    for (int i = 0; i < 2; i++)
#pragma unroll
        for (int j = 0; j < 4; j++) cc[i][j] = make_float4(0.f, 0.f, 0.f, 0.f);

#define LOADG(kb_) do {                                       \
    a0v = *(const float2*)&A[rA0 + (kb_) + tg * 2];           \
    a1v = *(const float2*)&A[rA1 + (kb_) + tg * 2];           \
    a2v = *(const float2*)&A[rA0 + (kb_) + 8 + tg * 2];       \
    a3v = *(const float2*)&A[rA1 + (kb_) + 8 + tg * 2];       \
    b0v = *(const float2*)&Wl[rB0 + (kb_) + tg * 2];          \
    b1v = *(const float2*)&Wl[rB0 + (kb_) + 8 + tg * 2];      \
} while (0)

#define STAGE(buf_) do {                                      \
    Af[((buf_) * 8 + warp) * 32 + lane] =                     \
        make_uint4(h2pack(a0v), h2pack(a1v), h2pack(a2v), h2pack(a3v)); \
    Bf[((buf_) * 8 + warp) * 32 + lane] = make_uint2(h2pack(b0v), h2pack(b1v)); \
} while (0)

    LOADG(0);
    STAGE(0);
    __syncthreads();

    for (int it = 0; it < 64; it++) {
        const int buf = it & 1;
        if (it < 63) LOADG((it + 1) * 16);

        uint4 aF0 = Af[(buf * 8 + wm * 2 + 0) * 32 + lane];
        uint4 aF1 = Af[(buf * 8 + wm * 2 + 1) * 32 + lane];
#pragma unroll
        for (int nt = 0; nt < 4; nt++) {
            uint2 bv = Bf[(buf * 8 + wn * 4 + nt) * 32 + lane];
            mma_f16(cc[0][nt], aF0, bv.x, bv.y);
            mma_f16(cc[1][nt], aF1, bv.x, bv.y);
        }
        if (it < 63) STAGE((it + 1) & 1);
        __syncthreads();
    }
#undef LOADG
#undef STAGE

#pragma unroll
    for (int mt = 0; mt < 2; mt++)
#pragma unroll
        for (int nt = 0; nt < 4; nt++) {
            const int row = m0 + wm * 32 + mt * 16 + g;
            const int col = n0 + wn * 32 + nt * 8 + 2 * tg;
            const float2 bias = *(const float2*)&bl[col];
            float4 v = cc[mt][nt];
            *(float2*)&C[(size_t)row * G_ + col] = make_float2(v.x + bias.x, v.y + bias.y);
            *(float2*)&C[(size_t)(row + 8) * G_ + col] = make_float2(v.z + bias.x, v.w + bias.y);
        }
}

// ---------------------------------------------------------------------------
// Persistent recurrence (2-term fp16), 256 thr, 128 blocks — R10 layout with
// a 3-buffer ring and ONE __syncthreads per 64-k chunk.
// ---------------------------------------------------------------------------
__global__ void __launch_bounds__(256, 1) lstm_seq(
    const float* __restrict__ Wl, const float* __restrict__ gin,
    const float* __restrict__ c0l, const float* __restrict__ h0l,
    ushort* __restrict__ hF0, ushort* __restrict__ hF1,
    float* __restrict__ layer_out, float* __restrict__ outp, int l)
{
    extern __shared__ float sm[];
    uint4*  WsH  = (uint4*)(sm + WH_OFF);
    uint4*  WsL  = (uint4*)(sm + WL_OFF);
    ushort* hbuf = (ushort*)(sm + HT_OFF);   // 3 bufs x (64 rows x 72 halfs)
    float*  gt   = sm + GT_OFF;
    float*  cs   = sm + CS_OFF;

    const int tid = threadIdx.x, jb = blockIdx.x;
    const int lane = tid & 31, warp = tid >> 5;
    const int wn = warp & 3, kw = warp >> 2;

    // --- W fragment staging (once per layer), fp16 hi/lo
#pragma unroll 1
    for (int q = 0; q < 16; q++) {
        const int fi = q * 256 + tid;
        const int ln = fi & 31, kc = (fi >> 5) & 63, mt = fi >> 11;
        const int colc = mt * 16 + (ln >> 2);
        const int colc8 = colc + 8;
        const int gr  = (colc  >> 3) * H_ + jb * 8 + (colc  & 7);
        const int gr8 = (colc8 >> 3) * H_ + jb * 8 + (colc8 & 7);
        const int k0 = kc * 16 + (ln & 3) * 2;
        const float* w0 = Wl + (size_t)gr  * K2_ + H_;
        const float* w8 = Wl + (size_t)gr8 * K2_ + H_;
        uint2 s0 = hsplit(*(const float2*)(w0 + k0));
        uint2 s1 = hsplit(*(const float2*)(w8 + k0));
        uint2 s2 = hsplit(*(const float2*)(w0 + k0 + 8));
        uint2 s3 = hsplit(*(const float2*)(w8 + k0 + 8));
        WsH[fi] = make_uint4(s0.x, s1.x, s2.x, s3.x);
        WsL[fi] = make_uint4(s0.y, s1.y, s2.y, s3.y);
    }
    for (int i = tid; i < 512; i += 256)
        cs[i] = c0l[(i >> 3) * H_ + jb * 8 + (i & 7)];
#pragma unroll
    for (int q = 0; q < 2; q++) {   // h0 -> parity-0 buffer (block's 8-k slice)
        const int idx = tid + q * 256;
        const int k = jb * 8 + (idx >> 6), b = idx & 63;
        __half hh = __float2half_rn(h0l[b * H_ + k]);
        hF0[b * 1024 + k] = *(ushort*)&hh;
    }

    const int b_pw = tid & 63;
    const int jj0  = (tid >> 6) * 2;
    const int sb = tid >> 2;                 // staging row 0..63
    const int sk0 = (tid & 3) * 16;          // halfs within 64-k chunk

    for (int t = 0; t < T_; t++) {
        const ushort* rH = (t & 1) ? hF1 : hF0;
        ushort*       wH = (t & 1) ? hF0 : hF1;

        const float* gp = gin + ((size_t)b_pw * T_ + t) * G_ + jb * 8 + jj0;
        float2 pf = __ldg((const float2*)gp);
        float2 pi = __ldg((const float2*)(gp + H_));
        float2 pg = __ldg((const float2*)(gp + 2 * H_));
        float2 po = __ldg((const float2*)(gp + 3 * H_));

        grid_barrier(jb);

        // prologue: chunks 0,1 -> bufs 0,1 (chunk = 64 b x 64 k fp16 = 8KB)
#pragma unroll
        for (int i = 0; i < 2; i++) {
            ushort* d = hbuf + i * 4608 + sb * 72 + sk0;
            const ushort* s = rH + sb * 1024 + i * 64 + sk0;
            cp_async16u(d, s);
            cp_async16u(d + 8, s + 8);
            asm volatile("cp.async.commit_group;");
        }

        float4 aHH[2][2], aLH[2][2];
#pragma unroll
        for (int i = 0; i < 2; i++)
#pragma unroll
            for (int j = 0; j < 2; j++) {
                aHH[i][j] = make_float4(0.f, 0.f, 0.f, 0.f);
                aLH[i][j] = make_float4(0.f, 0.f, 0.f, 0.f);
            }

#pragma unroll 1
        for (int c = 0; c < 16; c++) {
            if (c < 15) asm volatile("cp.async.wait_group 1;");
            else        asm volatile("cp.async.wait_group 0;");
            __syncthreads();   // chunk c ready; also WAR guard for buf (c+2)%3

            if (c < 14) {
                const int nb = (c + 2) % 3;
                ushort* d = hbuf + nb * 4608 + sb * 72 + sk0;
                const ushort* s = rH + sb * 1024 + (c + 2) * 64 + sk0;
                cp_async16u(d, s);
                cp_async16u(d + 8, s + 8);
                asm volatile("cp.async.commit_group;");
            }

            const ushort* hc = hbuf + (c % 3) * 4608;
#pragma unroll
            for (int r = 0; r < 2; r++) {
                const int kloc = 2 * r + kw;           // k16 within chunk
                const int kg = c * 4 + kloc;           // global k16 index
                uint4 aH0 = WsH[kg * 32 + lane];
                uint4 aH1 = WsH[(64 + kg) * 32 + lane];
                uint4 aL0 = WsL[kg * 32 + lane];
                uint4 aL1 = WsL[(64 + kg) * 32 + lane];
#pragma unroll
                for (int nt = 0; nt < 2; nt++) {
                    const int col = (wn * 2 + nt) * 8 + (lane >> 2);
                    const int off = col * 72 + kloc * 16 + (lane & 3) * 2;
                    uint b0 = *(const uint*)(hc + off);
                    uint b1 = *(const uint*)(hc + off + 8);
                    mma_f16(aHH[0][nt], aH0, b0, b1);
                    mma_f16(aHH[1][nt], aH1, b0, b1);
                    mma_f16(aLH[0][nt], aL0, b0, b1);
                    mma_f16(aLH[1][nt], aL1, b0, b1);
                }
            }
        }

        // gate partials -> slab (kw groups separate)
        float* slab = gt + kw * GT_GRP;
#pragma unroll
        for (int mt = 0; mt < 2; mt++)
#pragma unroll
            for (int nt = 0; nt < 2; nt++) {
                float4 v;
                v.x = aHH[mt][nt].x + aLH[mt][nt].x;
                v.y = aHH[mt][nt].y + aLH[mt][nt].y;
                v.z = aHH[mt][nt].z + aLH[mt][nt].z;
                v.w = aHH[mt][nt].w + aLH[mt][nt].w;
                const int colr = mt * 16 + (lane >> 2);
                const int bcol = (wn * 2 + nt) * 8 + (lane & 3) * 2;
                *(float2*)&slab[colr * 66 + bcol] = make_float2(v.x, v.y);
                *(float2*)&slab[(colr + 8) * 66 + bcol] = make_float2(v.z, v.w);
            }
        __syncthreads();

        // pointwise: thread owns batch b_pw, gate cols jj0, jj0+1
        float2 c_old = *(float2*)&cs[b_pw * 8 + jj0];
        float co[2] = {c_old.x, c_old.y};
        float gf[2] = {pf.x, pf.y}, gi2[2] = {pi.x, pi.y};
        float gg2[2] = {pg.x, pg.y}, go[2] = {po.x, po.y};
        float hv[2], cv[2];
#pragma unroll
        for (int j = 0; j < 2; j++) {
            const int jj = jj0 + j;
            float xf = gt[jj * 66 + b_pw]        + gt[GT_GRP + jj * 66 + b_pw]        + gf[j];
            float xi = gt[(8 + jj) * 66 + b_pw]  + gt[GT_GRP + (8 + jj) * 66 + b_pw]  + gi2[j];
            float xg = gt[(16 + jj) * 66 + b_pw] + gt[GT_GRP + (16 + jj) * 66 + b_pw] + gg2[j];
            float xo = gt[(24 + jj) * 66 + b_pw] + gt[GT_GRP + (24 + jj) * 66 + b_pw] + go[j];
            float f = sigmoidf_(xf), ig = sigmoidf_(xi);
            float gv = tanhf(xg),    o  = sigmoidf_(xo);
            cv[j] = f * co[j] + ig * gv;
            hv[j] = o * tanhf(cv[j]);
        }
        *(float2*)&cs[b_pw * 8 + jj0] = make_float2(cv[0], cv[1]);
        *(uint*)&wH[b_pw * 1024 + jb * 8 + jj0] = h2pack(make_float2(hv[0], hv[1]));
        *(float2*)&layer_out[((size_t)b_pw * T_ + t) * H_ + jb * 8 + jj0] =
            make_float2(hv[0], hv[1]);
        if (t == T_ - 1) {
            size_t hb2 = (size_t)B_ * T_ * H_ + (size_t)l * B_ * H_ +
                         (size_t)b_pw * H_ + jb * 8 + jj0;
            *(float2*)&outp[hb2] = make_float2(hv[0], hv[1]);
            *(float2*)&outp[hb2 + (size_t)L_ * B_ * H_] = make_float2(cv[0], cv[1]);
        }
    }
}

extern "C" void kernel_launch(void* const* d_in, const int* in_sizes, int n_in,
                              void* d_out, int out_size)
{
    const float* x  = (const float*)d_in[0];
    const float* W  = (const float*)d_in[1];
    const float* bs = (const float*)d_in[2];
    const float* h0 = (const float*)d_in[3];
    const float* c0 = (const float*)d_in[4];
    float* out = (float*)d_out;

    float *gin, *mid;
    ushort* hf;
    cudaGetSymbolAddress((void**)&gin, g_gin);
    cudaGetSymbolAddress((void**)&mid, g_mid);
    cudaGetSymbolAddress((void**)&hf, g_hf);
    ushort* hF0 = hf;
    ushort* hF1 = hf + B_ * H_;

    cudaFuncSetAttribute(lstm_seq, cudaFuncAttributeMaxDynamicSharedMemorySize,
                         SM_BYTES);

    for (int l = 0; l < L_; l++) {
        const float* layer_in  = (l == 0) ? x   : mid;
        float*       layer_out = (l == 0) ? mid : out;
        const float* Wl = W  + (size_t)l * G_ * K2_;
        const float* bl = bs + (size_t)l * G_;

        lstm_in_gemm<<<dim3(64, 256), 256>>>(layer_in, Wl, bl, gin);
        lstm_seq<<<NBLK, 256, SM_BYTES>>>(Wl, gin,
                                          c0 + (size_t)l * B_ * H_,
                                          h0 + (size_t)l * B_ * H_,
                                          hF0, hF1, layer_out, out, l);
    }
}

// round 14
// speedup vs baseline: 1.3385x; 1.1155x over previous
#include <cuda_runtime.h>
#include <cuda_fp16.h>
#include <math.h>
typedef unsigned int uint;
typedef unsigned short ushort;

#define B_   64
#define T_   512
#define H_   1024
#define L_   2
#define G_   4096
#define K2_  2048
#define NBLK 128

// lstm_seq smem plan (float units) — R10 layout
#define WH_OFF 0          // W hi fp16 fragments: 4096 uint4
#define WL_OFF 16384      // W lo fp16 fragments
#define HT_OFF 32768      // h ring: 2 bufs x 4608 halfs = 4608 floats
#define GT_OFF 37376      // gate exchange: 2 x 2112 floats
#define GT_GRP 2112
#define CS_OFF 41600      // cell state: 512 floats
#define SM_FLOATS 42112
#define SM_BYTES  (SM_FLOATS * 4)

__device__ float  g_gin[(size_t)B_ * T_ * G_];
__device__ float  g_mid[(size_t)B_ * T_ * H_];
__device__ ushort g_hf[2][B_ * H_];        // h single fp16, ping-pong parity
__device__ unsigned g_grp[256];            // 8 group counters, 128B apart
__device__ unsigned g_root = 0;
__device__ unsigned g_gen = 0;

__device__ __forceinline__ void mma_f16(float4& c, const uint4& a, uint b0, uint b1) {
    asm volatile(
        "mma.sync.aligned.m16n8k16.row.col.f32.f16.f16.f32 "
        "{%0,%1,%2,%3}, {%4,%5,%6,%7}, {%8,%9}, {%0,%1,%2,%3};"
        : "+f"(c.x), "+f"(c.y), "+f"(c.z), "+f"(c.w)
        : "r"(a.x), "r"(a.y), "r"(a.z), "r"(a.w), "r"(b0), "r"(b1));
}
__device__ __forceinline__ uint h2pack(float2 v) {
    __half2 h = __float22half2_rn(v);
    return *(uint*)&h;
}
__device__ __forceinline__ uint2 hsplit(float2 v) {
    __half2 h = __float22half2_rn(v);
    float lx = __half2float(__low2half(h));
    float ly = __half2float(__high2half(h));
    __half2 l = __float22half2_rn(make_float2(v.x - lx, v.y - ly));
    uint2 o;
    o.x = *(uint*)&h;
    o.y = *(uint*)&l;
    return o;
}
__device__ __forceinline__ float sigmoidf_(float x) { return __fdividef(1.0f, 1.0f + expf(-x)); }
__device__ __forceinline__ void cp_async16u(const ushort* smem_dst, const ushort* gsrc) {
    unsigned sa = (unsigned)__cvta_generic_to_shared((void*)smem_dst);
    asm volatile("cp.async.cg.shared.global [%0], [%1], 16;" :: "r"(sa), "l"(gsrc));
}

// Tree grid barrier: 8 padded group counters -> root -> release gen.
__device__ __forceinline__ void grid_barrier(int jb) {
    __syncthreads();
    if (threadIdx.x == 0) {
        asm volatile("fence.acq_rel.gpu;" ::: "memory");
        unsigned old;
        asm volatile("ld.relaxed.gpu.u32 %0, [%1];" : "=r"(old) : "l"(&g_gen));
        unsigned prev = atomicAdd(&g_grp[(jb & 7) * 32], 1u);
        bool done = false;
        if (prev == 15u) {
            unsigned pr = atomicAdd(&g_root, 1u);
            if (pr == 7u) {
#pragma unroll
                for (int i = 0; i < 8; i++)
                    asm volatile("st.relaxed.gpu.u32 [%0], %1;"
                                 :: "l"(&g_grp[i * 32]), "r"(0u));
                asm volatile("st.relaxed.gpu.u32 [%0], %1;" :: "l"(&g_root), "r"(0u));
                asm volatile("st.release.gpu.u32 [%0], %1;" :: "l"(&g_gen), "r"(old + 1u));
                done = true;
            }
        }
        if (!done) {
            unsigned cur;
            do { asm volatile("ld.acquire.gpu.u32 %0, [%1];" : "=r"(cur) : "l"(&g_gen)); }
            while (cur == old);
        }
    }
    __syncthreads();
}

// ---------------------------------------------------------------------------
// Input GEMM (single-term fp16): gin[m,n] = A[m,0:H].W[n,0:H] + bias[n]
// Block 128Mx64N, BK=16, 256 thr, warp tile 32x32. (R12 version — measured
// error cost acceptable: 4.19e-4 total)
// ---------------------------------------------------------------------------
__global__ void __launch_bounds__(256, 2) lstm_in_gemm(
    const float* __restrict__ A, const float* __restrict__ Wl,
    const float* __restrict__ bl, float* __restrict__ C)
{
    __shared__ uint4 Af[512];    // [buf2][mt8][lane32] fp16 A-frag
    __shared__ uint2 Bf[512];    // [buf2][nt8][lane32] = (b0h, b1h)

    const int tid = threadIdx.x, n0 = blockIdx.x * 64, m0 = blockIdx.y * 128;
    const int lane = tid & 31, warp = tid >> 5;
    const int wm = warp >> 1, wn = warp & 1;
    const int g = lane >> 2, tg = lane & 3;

    const size_t rA0 = (size_t)(m0 + warp * 16 + g) * H_;
    const size_t rA1 = rA0 + (size_t)8 * H_;
    const size_t rB0 = (size_t)(n0 + warp * 8 + g) * K2_;

    float2 a0v, a1v, a2v, a3v, b0v, b1v;
    float4 cc[2][4];
#pragma unroll
    for (int i = 0; i < 2; i++)
#pragma unroll
        for (int j = 0; j < 4; j++) cc[i][j] = make_float4(0.f, 0.f, 0.f, 0.f);

#define LOADG(kb_) do {                                       \
    a0v = *(const float2*)&A[rA0 + (kb_) + tg * 2];           \
    a1v = *(const float2*)&A[rA1 + (kb_) + tg * 2];           \
    a2v = *(const float2*)&A[rA0 + (kb_) + 8 + tg * 2];       \
    a3v = *(const float2*)&A[rA1 + (kb_) + 8 + tg * 2];       \
    b0v = *(const float2*)&Wl[rB0 + (kb_) + tg * 2];          \
    b1v = *(const float2*)&Wl[rB0 + (kb_) + 8 + tg * 2];      \
} while (0)

#define STAGE(buf_) do {                                      \
    Af[((buf_) * 8 + warp) * 32 + lane] =                     \
        make_uint4(h2pack(a0v), h2pack(a1v), h2pack(a2v), h2pack(a3v)); \
    Bf[((buf_) * 8 + warp) * 32 + lane] = make_uint2(h2pack(b0v), h2pack(b1v)); \
} while (0)

    LOADG(0);
    STAGE(0);
    __syncthreads();

    for (int it = 0; it < 64; it++) {
        const int buf = it & 1;
        if (it < 63) LOADG((it + 1) * 16);

        uint4 aF0 = Af[(buf * 8 + wm * 2 + 0) * 32 + lane];
        uint4 aF1 = Af[(buf * 8 + wm * 2 + 1) * 32 + lane];
#pragma unroll
        for (int nt = 0; nt < 4; nt++) {
            uint2 bv = Bf[(buf * 8 + wn * 4 + nt) * 32 + lane];
            mma_f16(cc[0][nt], aF0, bv.x, bv.y);
            mma_f16(cc[1][nt], aF1, bv.x, bv.y);
        }
        if (it < 63) STAGE((it + 1) & 1);
        __syncthreads();
    }
#undef LOADG
#undef STAGE

#pragma unroll
    for (int mt = 0; mt < 2; mt++)
#pragma unroll
        for (int nt = 0; nt < 4; nt++) {
            const int row = m0 + wm * 32 + mt * 16 + g;
            const int col = n0 + wn * 32 + nt * 8 + 2 * tg;
            const float2 bias = *(const float2*)&bl[col];
            float4 v = cc[mt][nt];
            *(float2*)&C[(size_t)row * G_ + col] = make_float2(v.x + bias.x, v.y + bias.y);
            *(float2*)&C[(size_t)(row + 8) * G_ + col] = make_float2(v.z + bias.x, v.w + bias.y);
        }
}

// ---------------------------------------------------------------------------
// Persistent recurrence (2-term fp16), 256 thr, 128 blocks — BYTE-IDENTICAL
// to R10 (best measured): 2-buffer ping-pong, cp.async issued BEFORE wait,
// 2 syncs per 64-k chunk.
// ---------------------------------------------------------------------------
__global__ void __launch_bounds__(256, 1) lstm_seq(
    const float* __restrict__ Wl, const float* __restrict__ gin,
    const float* __restrict__ c0l, const float* __restrict__ h0l,
    ushort* __restrict__ hF0, ushort* __restrict__ hF1,
    float* __restrict__ layer_out, float* __restrict__ outp, int l)
{
    extern __shared__ float sm[];
    uint4*  WsH  = (uint4*)(sm + WH_OFF);    // [mt2*64kg][lane32]
    uint4*  WsL  = (uint4*)(sm + WL_OFF);
    ushort* hbuf = (ushort*)(sm + HT_OFF);   // 2 bufs x (64 rows x 72 halfs)
    float*  gt   = sm + GT_OFF;
    float*  cs   = sm + CS_OFF;

    const int tid = threadIdx.x, jb = blockIdx.x;
    const int lane = tid & 31, warp = tid >> 5;
    const int wn = warp & 3, kw = warp >> 2;

    // --- W fragment staging (once per layer), fp16 hi/lo
#pragma unroll 1
    for (int q = 0; q < 16; q++) {
        const int fi = q * 256 + tid;
        const int ln = fi & 31, kc = (fi >> 5) & 63, mt = fi >> 11;
        const int colc = mt * 16 + (ln >> 2);
        const int colc8 = colc + 8;
        const int gr  = (colc  >> 3) * H_ + jb * 8 + (colc  & 7);
        const int gr8 = (colc8 >> 3) * H_ + jb * 8 + (colc8 & 7);
        const int k0 = kc * 16 + (ln & 3) * 2;
        const float* w0 = Wl + (size_t)gr  * K2_ + H_;
        const float* w8 = Wl + (size_t)gr8 * K2_ + H_;
        uint2 s0 = hsplit(*(const float2*)(w0 + k0));
        uint2 s1 = hsplit(*(const float2*)(w8 + k0));
        uint2 s2 = hsplit(*(const float2*)(w0 + k0 + 8));
        uint2 s3 = hsplit(*(const float2*)(w8 + k0 + 8));
        WsH[fi] = make_uint4(s0.x, s1.x, s2.x, s3.x);
        WsL[fi] = make_uint4(s0.y, s1.y, s2.y, s3.y);
    }
    for (int i = tid; i < 512; i += 256)
        cs[i] = c0l[(i >> 3) * H_ + jb * 8 + (i & 7)];
    // h0 -> parity-0 buffer as single fp16 (this block's k slice)
#pragma unroll
    for (int q = 0; q < 2; q++) {
        const int idx = tid + q * 256;
        const int k = jb * 8 + (idx >> 6), b = idx & 63;
        __half hh = __float2half_rn(h0l[b * H_ + k]);
        hF0[b * 1024 + k] = *(ushort*)&hh;
    }

    const int b_pw = tid & 63;
    const int jj0  = (tid >> 6) * 2;
    const int sb = tid >> 2;                 // staging row 0..63
    const int sk0 = (tid & 3) * 16;          // halfs: segments at sk0, sk0+8

    for (int t = 0; t < T_; t++) {
        const ushort* rH = (t & 1) ? hF1 : hF0;
        ushort*       wH = (t & 1) ? hF0 : hF1;

        const float* gp = gin + ((size_t)b_pw * T_ + t) * G_ + jb * 8 + jj0;
        float2 pf = __ldg((const float2*)gp);
        float2 pi = __ldg((const float2*)(gp + H_));
        float2 pg = __ldg((const float2*)(gp + 2 * H_));
        float2 po = __ldg((const float2*)(gp + 3 * H_));

        grid_barrier(jb);

        // stage chunk 0 (64 k x 64 b singles = 8KB)
        cp_async16u(hbuf + sb * 72 + sk0,     rH + sb * 1024 + sk0);
        cp_async16u(hbuf + sb * 72 + sk0 + 8, rH + sb * 1024 + sk0 + 8);
        asm volatile("cp.async.commit_group;");

        float4 aHH[2][2], aLH[2][2];
#pragma unroll
        for (int i = 0; i < 2; i++)
#pragma unroll
            for (int j = 0; j < 2; j++) {
                aHH[i][j] = make_float4(0.f, 0.f, 0.f, 0.f);
                aLH[i][j] = make_float4(0.f, 0.f, 0.f, 0.f);
            }

        for (int kt = 0; kt < 16; kt++) {
            const ushort* hc = hbuf + (kt & 1) * 4608;
            if (kt < 15) {
                const int nb = (kt + 1) & 1;
                const ushort* src = rH + (kt + 1) * 64;
                cp_async16u(hbuf + nb * 4608 + sb * 72 + sk0,     src + sb * 1024 + sk0);
                cp_async16u(hbuf + nb * 4608 + sb * 72 + sk0 + 8, src + sb * 1024 + sk0 + 8);
                asm volatile("cp.async.commit_group;");
                asm volatile("cp.async.wait_group 1;");
            } else {
                asm volatile("cp.async.wait_group 0;");
            }
            __syncthreads();

#pragma unroll
            for (int r = 0; r < 2; r++) {
                const int kloc = 2 * r + kw;
                const int kg = kt * 4 + kloc;
                uint4 aH0 = WsH[kg * 32 + lane];
                uint4 aH1 = WsH[(64 + kg) * 32 + lane];
                uint4 aL0 = WsL[kg * 32 + lane];
                uint4 aL1 = WsL[(64 + kg) * 32 + lane];
#pragma unroll
                for (int nt = 0; nt < 2; nt++) {
                    const int col = (wn * 2 + nt) * 8 + (lane >> 2);
                    const int off = col * 72 + kloc * 16 + (lane & 3) * 2;
                    uint b0 = *(const uint*)(hc + off);
                    uint b1 = *(const uint*)(hc + off + 8);
                    mma_f16(aHH[0][nt], aH0, b0, b1);
                    mma_f16(aHH[1][nt], aH1, b0, b1);
                    mma_f16(aLH[0][nt], aL0, b0, b1);
                    mma_f16(aLH[1][nt], aL1, b0, b1);
                }
            }
            __syncthreads();
        }

        // gate partials -> slab (kw groups separate)
        float* slab = gt + kw * GT_GRP;
#pragma unroll
        for (int mt = 0; mt < 2; mt++)
#pragma unroll
            for (int nt = 0; nt < 2; nt++) {
                float4 v;
                v.x = aHH[mt][nt].x + aLH[mt][nt].x;
                v.y = aHH[mt][nt].y + aLH[mt][nt].y;
                v.z = aHH[mt][nt].z + aLH[mt][nt].z;
                v.w = aHH[mt][nt].w + aLH[mt][nt].w;
                const int colr = mt * 16 + (lane >> 2);
                const int bcol = (wn * 2 + nt) * 8 + (lane & 3) * 2;
                *(float2*)&slab[colr * 66 + bcol] = make_float2(v.x, v.y);
                *(float2*)&slab[(colr + 8) * 66 + bcol] = make_float2(v.z, v.w);
            }
        __syncthreads();

        // pointwise: thread owns batch b_pw, gate cols jj0, jj0+1
        float2 c_old = *(float2*)&cs[b_pw * 8 + jj0];
        float co[2] = {c_old.x, c_old.y};
        float gf[2] = {pf.x, pf.y}, gi2[2] = {pi.x, pi.y};
        float gg2[2] = {pg.x, pg.y}, go[2] = {po.x, po.y};
        float hv[2], cv[2];
#pragma unroll
        for (int j = 0; j < 2; j++) {
            const int jj = jj0 + j;
            float xf = gt[jj * 66 + b_pw]        + gt[GT_GRP + jj * 66 + b_pw]        + gf[j];
            float xi = gt[(8 + jj) * 66 + b_pw]  + gt[GT_GRP + (8 + jj) * 66 + b_pw]  + gi2[j];
            float xg = gt[(16 + jj) * 66 + b_pw] + gt[GT_GRP + (16 + jj) * 66 + b_pw] + gg2[j];
            float xo = gt[(24 + jj) * 66 + b_pw] + gt[GT_GRP + (24 + jj) * 66 + b_pw] + go[j];
            float f = sigmoidf_(xf), ig = sigmoidf_(xi);
            float gv = tanhf(xg),    o  = sigmoidf_(xo);
            cv[j] = f * co[j] + ig * gv;
            hv[j] = o * tanhf(cv[j]);
        }
        *(float2*)&cs[b_pw * 8 + jj0] = make_float2(cv[0], cv[1]);
        *(uint*)&wH[b_pw * 1024 + jb * 8 + jj0] = h2pack(make_float2(hv[0], hv[1]));
        *(float2*)&layer_out[((size_t)b_pw * T_ + t) * H_ + jb * 8 + jj0] =
            make_float2(hv[0], hv[1]);
        if (t == T_ - 1) {
            size_t hb2 = (size_t)B_ * T_ * H_ + (size_t)l * B_ * H_ +
                         (size_t)b_pw * H_ + jb * 8 + jj0;
            *(float2*)&outp[hb2] = make_float2(hv[0], hv[1]);
            *(float2*)&outp[hb2 + (size_t)L_ * B_ * H_] = make_float2(cv[0], cv[1]);
        }
    }
}

extern "C" void kernel_launch(void* const* d_in, const int* in_sizes, int n_in,
                              void* d_out, int out_size)
{
    const float* x  = (const float*)d_in[0];
    const float* W  = (const float*)d_in[1];
    const float* bs = (const float*)d_in[2];
    const float* h0 = (const float*)d_in[3];
    const float* c0 = (const float*)d_in[4];
    float* out = (float*)d_out;

    float *gin, *mid;
    ushort* hf;
    cudaGetSymbolAddress((void**)&gin, g_gin);
    cudaGetSymbolAddress((void**)&mid, g_mid);
    cudaGetSymbolAddress((void**)&hf, g_hf);
    ushort* hF0 = hf;
    ushort* hF1 = hf + B_ * H_;

    cudaFuncSetAttribute(lstm_seq, cudaFuncAttributeMaxDynamicSharedMemorySize,
                         SM_BYTES);

    for (int l = 0; l < L_; l++) {
        const float* layer_in  = (l == 0) ? x   : mid;
        float*       layer_out = (l == 0) ? mid : out;
        const float* Wl = W  + (size_t)l * G_ * K2_;
        const float* bl = bs + (size_t)l * G_;

        lstm_in_gemm<<<dim3(64, 256), 256>>>(layer_in, Wl, bl, gin);
        lstm_seq<<<NBLK, 256, SM_BYTES>>>(Wl, gin,
                                          c0 + (size_t)l * B_ * H_,
                                          h0 + (size_t)l * B_ * H_,
                                          hF0, hF1, layer_out, out, l);
    }
}

// round 15
// speedup vs baseline: 1.3590x; 1.0153x over previous
#include <cuda_runtime.h>
#include <cuda_fp16.h>
#include <math.h>
typedef unsigned int uint;
typedef unsigned short ushort;

#define B_   64
#define T_   512
#define H_   1024
#define L_   2
#define G_   4096
#define K2_  2048
#define NBLK 128

// lstm_seq smem plan (float units) — R13 layout kept (WL region unused now,
// which also keeps the smem request large enough to force 1 block/SM)
#define WH_OFF 0          // W fp16 fragments: 4096 uint4
#define WL_OFF 16384      // (unused)
#define HT_OFF 32768      // h ring: 2 bufs x 4608 halfs
#define GT_OFF 37376      // gate exchange: 2 x 2112 floats
#define GT_GRP 2112
#define CS_OFF 41600      // cell state: 512 floats
#define SM_FLOATS 42112
#define SM_BYTES  (SM_FLOATS * 4)

__device__ float  g_gin[(size_t)B_ * T_ * G_];
__device__ float  g_mid[(size_t)B_ * T_ * H_];
__device__ ushort g_hf[2][B_ * H_];        // h single fp16, ping-pong parity
__device__ unsigned g_grp[256];            // 8 group counters, 128B apart
__device__ unsigned g_root = 0;
__device__ unsigned g_gen = 0;

__device__ __forceinline__ void mma_f16(float4& c, const uint4& a, uint b0, uint b1) {
    asm volatile(
        "mma.sync.aligned.m16n8k16.row.col.f32.f16.f16.f32 "
        "{%0,%1,%2,%3}, {%4,%5,%6,%7}, {%8,%9}, {%0,%1,%2,%3};"
        : "+f"(c.x), "+f"(c.y), "+f"(c.z), "+f"(c.w)
        : "r"(a.x), "r"(a.y), "r"(a.z), "r"(a.w), "r"(b0), "r"(b1));
}
__device__ __forceinline__ uint h2pack(float2 v) {
    __half2 h = __float22half2_rn(v);
    return *(uint*)&h;
}
__device__ __forceinline__ float sigmoidf_(float x) { return __fdividef(1.0f, 1.0f + expf(-x)); }
__device__ __forceinline__ void cp_async16u(const ushort* smem_dst, const ushort* gsrc) {
    unsigned sa = (unsigned)__cvta_generic_to_shared((void*)smem_dst);
    asm volatile("cp.async.cg.shared.global [%0], [%1], 16;" :: "r"(sa), "l"(gsrc));
}

// Tree grid barrier: 8 padded group counters -> root -> release gen.
__device__ __forceinline__ void grid_barrier(int jb) {
    __syncthreads();
    if (threadIdx.x == 0) {
        asm volatile("fence.acq_rel.gpu;" ::: "memory");
        unsigned old;
        asm volatile("ld.relaxed.gpu.u32 %0, [%1];" : "=r"(old) : "l"(&g_gen));
        unsigned prev = atomicAdd(&g_grp[(jb & 7) * 32], 1u);
        bool done = false;
        if (prev == 15u) {
            unsigned pr = atomicAdd(&g_root, 1u);
            if (pr == 7u) {
#pragma unroll
                for (int i = 0; i < 8; i++)
                    asm volatile("st.relaxed.gpu.u32 [%0], %1;"
                                 :: "l"(&g_grp[i * 32]), "r"(0u));
                asm volatile("st.relaxed.gpu.u32 [%0], %1;" :: "l"(&g_root), "r"(0u));
                asm volatile("st.release.gpu.u32 [%0], %1;" :: "l"(&g_gen), "r"(old + 1u));
                done = true;
            }
        }
        if (!done) {
            unsigned cur;
            do { asm volatile("ld.acquire.gpu.u32 %0, [%1];" : "=r"(cur) : "l"(&g_gen)); }
            while (cur == old);
        }
    }
    __syncthreads();
}

// ---------------------------------------------------------------------------
// Input GEMM (single-term fp16) — unchanged from R13 (passing, 4.19e-4).
// ---------------------------------------------------------------------------
__global__ void __launch_bounds__(256, 2) lstm_in_gemm(
    const float* __restrict__ A, const float* __restrict__ Wl,
    const float* __restrict__ bl, float* __restrict__ C)
{
    __shared__ uint4 Af[512];    // [buf2][mt8][lane32] fp16 A-frag
    __shared__ uint2 Bf[512];    // [buf2][nt8][lane32] = (b0h, b1h)

    const int tid = threadIdx.x, n0 = blockIdx.x * 64, m0 = blockIdx.y * 128;
    const int lane = tid & 31, warp = tid >> 5;
    const int wm = warp >> 1, wn = warp & 1;
    const int g = lane >> 2, tg = lane & 3;

    const size_t rA0 = (size_t)(m0 + warp * 16 + g) * H_;
    const size_t rA1 = rA0 + (size_t)8 * H_;
    const size_t rB0 = (size_t)(n0 + warp * 8 + g) * K2_;

    float2 a0v, a1v, a2v, a3v, b0v, b1v;
    float4 cc[2][4];
#pragma unroll
    for (int i = 0; i < 2; i++)
#pragma unroll
        for (int j = 0; j < 4; j++) cc[i][j] = make_float4(0.f, 0.f, 0.f, 0.f);

#define LOADG(kb_) do {                                       \
    a0v = *(const float2*)&A[rA0 + (kb_) + tg * 2];           \
    a1v = *(const float2*)&A[rA1 + (kb_) + tg * 2];           \
    a2v = *(const float2*)&A[rA0 + (kb_) + 8 + tg * 2];       \
    a3v = *(const float2*)&A[rA1 + (kb_) + 8 + tg * 2];       \
    b0v = *(const float2*)&Wl[rB0 + (kb_) + tg * 2];          \
    b1v = *(const float2*)&Wl[rB0 + (kb_) + 8 + tg * 2];      \
} while (0)

#define STAGE(buf_) do {                                      \
    Af[((buf_) * 8 + warp) * 32 + lane] =                     \
        make_uint4(h2pack(a0v), h2pack(a1v), h2pack(a2v), h2pack(a3v)); \
    Bf[((buf_) * 8 + warp) * 32 + lane] = make_uint2(h2pack(b0v), h2pack(b1v)); \
} while (0)

    LOADG(0);
    STAGE(0);
    __syncthreads();

    for (int it = 0; it < 64; it++) {
        const int buf = it & 1;
        if (it < 63) LOADG((it + 1) * 16);

        uint4 aF0 = Af[(buf * 8 + wm * 2 + 0) * 32 + lane];
        uint4 aF1 = Af[(buf * 8 + wm * 2 + 1) * 32 + lane];
#pragma unroll
        for (int nt = 0; nt < 4; nt++) {
            uint2 bv = Bf[(buf * 8 + wn * 4 + nt) * 32 + lane];
            mma_f16(cc[0][nt], aF0, bv.x, bv.y);
            mma_f16(cc[1][nt], aF1, bv.x, bv.y);
        }
        if (it < 63) STAGE((it + 1) & 1);
        __syncthreads();
    }
#undef LOADG
#undef STAGE

#pragma unroll
    for (int mt = 0; mt < 2; mt++)
#pragma unroll
        for (int nt = 0; nt < 4; nt++) {
            const int row = m0 + wm * 32 + mt * 16 + g;
            const int col = n0 + wn * 32 + nt * 8 + 2 * tg;
            const float2 bias = *(const float2*)&bl[col];
            float4 v = cc[mt][nt];
            *(float2*)&C[(size_t)row * G_ + col] = make_float2(v.x + bias.x, v.y + bias.y);
            *(float2*)&C[(size_t)(row + 8) * G_ + col] = make_float2(v.z + bias.x, v.w + bias.y);
        }
}

// ---------------------------------------------------------------------------
// Persistent recurrence — R13/R10 loop with the W lo-term REMOVED (1-term
// fp16 W). Everything else (pipeline, syncs, exchange, pointwise) identical.
// ---------------------------------------------------------------------------
__global__ void __launch_bounds__(256, 1) lstm_seq(
    const float* __restrict__ Wl, const float* __restrict__ gin,
    const float* __restrict__ c0l, const float* __restrict__ h0l,
    ushort* __restrict__ hF0, ushort* __restrict__ hF1,
    float* __restrict__ layer_out, float* __restrict__ outp, int l)
{
    extern __shared__ float sm[];
    uint4*  WsH  = (uint4*)(sm + WH_OFF);    // [mt2*64kg][lane32]
    ushort* hbuf = (ushort*)(sm + HT_OFF);   // 2 bufs x (64 rows x 72 halfs)
    float*  gt   = sm + GT_OFF;
    float*  cs   = sm + CS_OFF;

    const int tid = threadIdx.x, jb = blockIdx.x;
    const int lane = tid & 31, warp = tid >> 5;
    const int wn = warp & 3, kw = warp >> 2;

    // --- W fragment staging (once per layer), single fp16
#pragma unroll 1
    for (int q = 0; q < 16; q++) {
        const int fi = q * 256 + tid;
        const int ln = fi & 31, kc = (fi >> 5) & 63, mt = fi >> 11;
        const int colc = mt * 16 + (ln >> 2);
        const int colc8 = colc + 8;
        const int gr  = (colc  >> 3) * H_ + jb * 8 + (colc  & 7);
        const int gr8 = (colc8 >> 3) * H_ + jb * 8 + (colc8 & 7);
        const int k0 = kc * 16 + (ln & 3) * 2;
        const float* w0 = Wl + (size_t)gr  * K2_ + H_;
        const float* w8 = Wl + (size_t)gr8 * K2_ + H_;
        uint p0 = h2pack(*(const float2*)(w0 + k0));
        uint p1 = h2pack(*(const float2*)(w8 + k0));
        uint p2 = h2pack(*(const float2*)(w0 + k0 + 8));
        uint p3 = h2pack(*(const float2*)(w8 + k0 + 8));
        WsH[fi] = make_uint4(p0, p1, p2, p3);
    }
    for (int i = tid; i < 512; i += 256)
        cs[i] = c0l[(i >> 3) * H_ + jb * 8 + (i & 7)];
    // h0 -> parity-0 buffer as single fp16 (this block's k slice)
#pragma unroll
    for (int q = 0; q < 2; q++) {
        const int idx = tid + q * 256;
        const int k = jb * 8 + (idx >> 6), b = idx & 63;
        __half hh = __float2half_rn(h0l[b * H_ + k]);
        hF0[b * 1024 + k] = *(ushort*)&hh;
    }

    const int b_pw = tid & 63;
    const int jj0  = (tid >> 6) * 2;
    const int sb = tid >> 2;                 // staging row 0..63
    const int sk0 = (tid & 3) * 16;          // halfs: segments at sk0, sk0+8

    for (int t = 0; t < T_; t++) {
        const ushort* rH = (t & 1) ? hF1 : hF0;
        ushort*       wH = (t & 1) ? hF0 : hF1;

        const float* gp = gin + ((size_t)b_pw * T_ + t) * G_ + jb * 8 + jj0;
        float2 pf = __ldg((const float2*)gp);
        float2 pi = __ldg((const float2*)(gp + H_));
        float2 pg = __ldg((const float2*)(gp + 2 * H_));
        float2 po = __ldg((const float2*)(gp + 3 * H_));

        grid_barrier(jb);

        // stage chunk 0 (64 k x 64 b singles = 8KB)
        cp_async16u(hbuf + sb * 72 + sk0,     rH + sb * 1024 + sk0);
        cp_async16u(hbuf + sb * 72 + sk0 + 8, rH + sb * 1024 + sk0 + 8);
        asm volatile("cp.async.commit_group;");

        float4 aHH[2][2];
#pragma unroll
        for (int i = 0; i < 2; i++)
#pragma unroll
            for (int j = 0; j < 2; j++)
                aHH[i][j] = make_float4(0.f, 0.f, 0.f, 0.f);

        for (int kt = 0; kt < 16; kt++) {
            const ushort* hc = hbuf + (kt & 1) * 4608;
            if (kt < 15) {
                const int nb = (kt + 1) & 1;
                const ushort* src = rH + (kt + 1) * 64;
                cp_async16u(hbuf + nb * 4608 + sb * 72 + sk0,     src + sb * 1024 + sk0);
                cp_async16u(hbuf + nb * 4608 + sb * 72 + sk0 + 8, src + sb * 1024 + sk0 + 8);
                asm volatile("cp.async.commit_group;");
                asm volatile("cp.async.wait_group 1;");
            } else {
                asm volatile("cp.async.wait_group 0;");
            }
            __syncthreads();

#pragma unroll
            for (int r = 0; r < 2; r++) {
                const int kloc = 2 * r + kw;
                const int kg = kt * 4 + kloc;
                uint4 aH0 = WsH[kg * 32 + lane];
                uint4 aH1 = WsH[(64 + kg) * 32 + lane];
#pragma unroll
                for (int nt = 0; nt < 2; nt++) {
                    const int col = (wn * 2 + nt) * 8 + (lane >> 2);
                    const int off = col * 72 + kloc * 16 + (lane & 3) * 2;
                    uint b0 = *(const uint*)(hc + off);
                    uint b1 = *(const uint*)(hc + off + 8);
                    mma_f16(aHH[0][nt], aH0, b0, b1);
                    mma_f16(aHH[1][nt], aH1, b0, b1);
                }
            }
            __syncthreads();
        }

        // gate partials -> slab (kw groups separate)
        float* slab = gt + kw * GT_GRP;
#pragma unroll
        for (int mt = 0; mt < 2; mt++)
#pragma unroll
            for (int nt = 0; nt < 2; nt++) {
                float4 v = aHH[mt][nt];
                const int colr = mt * 16 + (lane >> 2);
                const int bcol = (wn * 2 + nt) * 8 + (lane & 3) * 2;
                *(float2*)&slab[colr * 66 + bcol] = make_float2(v.x, v.y);
                *(float2*)&slab[(colr + 8) * 66 + bcol] = make_float2(v.z, v.w);
            }
        __syncthreads();

        // pointwise: thread owns batch b_pw, gate cols jj0, jj0+1
        float2 c_old = *(float2*)&cs[b_pw * 8 + jj0];
        float co[2] = {c_old.x, c_old.y};
        float gf[2] = {pf.x, pf.y}, gi2[2] = {pi.x, pi.y};
        float gg2[2] = {pg.x, pg.y}, go[2] = {po.x, po.y};
        float hv[2], cv[2];
#pragma unroll
        for (int j = 0; j < 2; j++) {
            const int jj = jj0 + j;
            float xf = gt[jj * 66 + b_pw]        + gt[GT_GRP + jj * 66 + b_pw]        + gf[j];
            float xi = gt[(8 + jj) * 66 + b_pw]  + gt[GT_GRP + (8 + jj) * 66 + b_pw]  + gi2[j];
            float xg = gt[(16 + jj) * 66 + b_pw] + gt[GT_GRP + (16 + jj) * 66 + b_pw] + gg2[j];
            float xo = gt[(24 + jj) * 66 + b_pw] + gt[GT_GRP + (24 + jj) * 66 + b_pw] + go[j];
            float f = sigmoidf_(xf), ig = sigmoidf_(xi);
            float gv = tanhf(xg),    o  = sigmoidf_(xo);
            cv[j] = f * co[j] + ig * gv;
            hv[j] = o * tanhf(cv[j]);
        }
        *(float2*)&cs[b_pw * 8 + jj0] = make_float2(cv[0], cv[1]);
        *(uint*)&wH[b_pw * 1024 + jb * 8 + jj0] = h2pack(make_float2(hv[0], hv[1]));
        *(float2*)&layer_out[((size_t)b_pw * T_ + t) * H_ + jb * 8 + jj0] =
            make_float2(hv[0], hv[1]);
        if (t == T_ - 1) {
            size_t hb2 = (size_t)B_ * T_ * H_ + (size_t)l * B_ * H_ +
                         (size_t)b_pw * H_ + jb * 8 + jj0;
            *(float2*)&outp[hb2] = make_float2(hv[0], hv[1]);
            *(float2*)&outp[hb2 + (size_t)L_ * B_ * H_] = make_float2(cv[0], cv[1]);
        }
    }
}

extern "C" void kernel_launch(void* const* d_in, const int* in_sizes, int n_in,
                              void* d_out, int out_size)
{
    const float* x  = (const float*)d_in[0];
    const float* W  = (const float*)d_in[1];
    const float* bs = (const float*)d_in[2];
    const float* h0 = (const float*)d_in[3];
    const float* c0 = (const float*)d_in[4];
    float* out = (float*)d_out;

    float *gin, *mid;
    ushort* hf;
    cudaGetSymbolAddress((void**)&gin, g_gin);
    cudaGetSymbolAddress((void**)&mid, g_mid);
    cudaGetSymbolAddress((void**)&hf, g_hf);
    ushort* hF0 = hf;
    ushort* hF1 = hf + B_ * H_;

    cudaFuncSetAttribute(lstm_seq, cudaFuncAttributeMaxDynamicSharedMemorySize,
                         SM_BYTES);

    for (int l = 0; l < L_; l++) {
        const float* layer_in  = (l == 0) ? x   : mid;
        float*       layer_out = (l == 0) ? mid : out;
        const float* Wl = W  + (size_t)l * G_ * K2_;
        const float* bl = bs + (size_t)l * G_;

        lstm_in_gemm<<<dim3(64, 256), 256>>>(layer_in, Wl, bl, gin);
        lstm_seq<<<NBLK, 256, SM_BYTES>>>(Wl, gin,
                                          c0 + (size_t)l * B_ * H_,
                                          h0 + (size_t)l * B_ * H_,
                                          hF0, hF1, layer_out, out, l);
    }
}